// round 6
// baseline (speedup 1.0000x reference)
#include <cuda_runtime.h>
#include <cstdint>

// ---------------------------------------------------------------------------
// MPS_33930241638883: 20-qubit staircase, K=1. Bond-dim-2 MPS closed form:
//   psi(x0..x19) = e_{x19}^T . T[x18] ... T[x1] . v(x0)
// T[x]_{t,s} = U[2x+t, 2s], v(x0)_s = U[2x0+s, 0]; x_w = bit (19-w) of n.
// n = g*512 + j: g holds x0..x10, j holds x11..x19 (x19 = j bit 0).
//
// Warp-specialized latency-optimized kernel, 512 blocks (1 wave):
//  - warps 0-3: gate build (2 elems/thread), 4-round tree matmul (T folded),
//    quad table Q[d3d2d1d0]=T[d3]T[d2]T[d1]T[d0], split-parallel heads,
//    all under bar.sync 1,128 (warps 4-7 wait at ONE __syncthreads).
//  - all threads: tail matrix O = Q.Q, 8 outputs |row(O).ab(g)|^2, coalesced.
// ---------------------------------------------------------------------------

__device__ __forceinline__ float2 cmul(float2 a, float2 b) {
    return make_float2(a.x * b.x - a.y * b.y, a.x * b.y + a.y * b.x);
}
__device__ __forceinline__ float2 cadd(float2 a, float2 b) {
    return make_float2(a.x + b.x, a.y + b.y);
}
__device__ __forceinline__ float2 cfma2(float2 a, float2 b, float2 acc) {
    acc.x = fmaf(a.x, b.x, fmaf(-a.y, b.y, acc.x));
    acc.y = fmaf(a.x, b.y, fmaf(a.y, b.x, acc.y));
    return acc;
}
__device__ __forceinline__ int rev4(int v) {
    return ((v & 1) << 3) | ((v & 2) << 1) | ((v & 4) >> 1) | ((v & 8) >> 3);
}
#define BAR128() asm volatile("bar.sync 1, 128;" ::: "memory")

// basis-change 2x2: p=1 X->RY(-pi/2), p=2 Y->RX(+pi/2), p=3 Z->I
__device__ __forceinline__ float2 basisB(int p, int i, int j) {
    const float C = 0.70710678118654752f;
    if (p == 1) {
        return make_float2((i == 1 && j == 0) ? -C : C, 0.f);
    } else if (p == 2) {
        return (i == j) ? make_float2(C, 0.f) : make_float2(0.f, -C);
    } else {
        return (i == j) ? make_float2(1.f, 0.f) : make_float2(0.f, 0.f);
    }
}

// rotation 2x2: p=1 RX, p=2 RY, p=3 RZ
__device__ __forceinline__ float2 rotR(int p, int i, int j, float ch, float sh) {
    if (p == 1) {
        return (i == j) ? make_float2(ch, 0.f) : make_float2(0.f, -sh);
    } else if (p == 2) {
        if (i == j) return make_float2(ch, 0.f);
        return (i == 0) ? make_float2(-sh, 0.f) : make_float2(sh, 0.f);
    } else {
        if (i != j) return make_float2(0.f, 0.f);
        return (j == 0) ? make_float2(ch, -sh) : make_float2(ch, sh);
    }
}

// element (r,c) of gate i's 4x4 matrix (verified rounds 1/2/4/5)
__device__ __forceinline__ float2 gateElem(int i, int r, int c, float ch, float sh) {
    int p0, p1;
    if (i < 3) { p0 = 0; p1 = i + 1; }
    else       { p0 = ((i - 3) >> 2) + 1; p1 = (i - 3) & 3; }
    const int ar = r >> 1, br = r & 1, ac = c >> 1, bc = c & 1;

    if (p0 == 0)
        return (ar == ac) ? rotR(p1, br, bc, ch, sh) : make_float2(0.f, 0.f);
    if (p1 == 0)
        return (br == bc) ? rotR(p0, ar, ac, ch, sh) : make_float2(0.f, 0.f);

    float2 acc = make_float2(0.f, 0.f);
    #pragma unroll
    for (int k = 0; k < 4; k++) {
        const int ak = k >> 1, bk = k & 1;
        float2 Prk = cmul(basisB(p0, ar, ak), basisB(p1, br, bk));
        float2 Pkc = cmul(basisB(p0, ak, ac), basisB(p1, bk, bc));
        float2 Dk = (k == 0 || k == 3) ? make_float2(ch, -sh) : make_float2(ch, sh);
        acc = cadd(acc, cmul(cmul(Prk, Dk), Pkc));
    }
    return acc;
}

__global__ void __launch_bounds__(256, 8) mps_kernel(const float* __restrict__ params,
                                                     float* __restrict__ out) {
    __shared__ float2 bufA[256];   // gates / tree ping (U ends in bufA[0..15])
    __shared__ float2 bufB[128];   // tree pong
    __shared__ float2 sT[8];       // T[b] at b*4 + row*2 + col
    __shared__ float2 sQ[64];      // Q[q] at q*4 + r*2 + c ; q = d3d2d1d0 (d3 left)
    __shared__ float2 sAB[8];      // head vectors (4 groups x 2)
    __shared__ float2 sL[16];      // left-half head matrices (4 groups x 4)

    const int tid = threadIdx.x;

    if (tid < 128) {
        // ---- gate build: 2 consecutive elems of the SAME gate per thread ----
        {
            const int m = tid >> 3;              // 0..15
            const int e0 = (tid << 1) & 15;      // even elem
            float2 g0, g1;
            if (m < 15) {
                float th = __ldg(&params[m]);
                float sh, ch;
                sincosf(0.5f * th, &sh, &ch);
                g0 = gateElem(m, e0 >> 2, e0 & 3, ch, sh);
                g1 = gateElem(m, (e0 + 1) >> 2, (e0 + 1) & 3, ch, sh);
            } else {
                g0 = (e0 >> 2 == (e0 & 3)) ? make_float2(1.f, 0.f) : make_float2(0.f, 0.f);
                g1 = ((e0 + 1) >> 2 == ((e0 + 1) & 3)) ? make_float2(1.f, 0.f)
                                                        : make_float2(0.f, 0.f);
            }
            bufA[tid * 2]     = g0;
            bufA[tid * 2 + 1] = g1;
        }
        BAR128();

        // ---- round 1: 8 products (128 elems) ----
        {
            const int m = tid >> 4, r = (tid >> 2) & 3, c = tid & 3;
            float2 acc = make_float2(0.f, 0.f);
            #pragma unroll
            for (int k = 0; k < 4; k++)
                acc = cfma2(bufA[(2 * m + 1) * 16 + r * 4 + k],
                            bufA[(2 * m) * 16 + k * 4 + c], acc);
            bufB[tid] = acc;
        }
        BAR128();

        // ---- round 2: 4 products (64 elems) ----
        if (tid < 64) {
            const int m = tid >> 4, r = (tid >> 2) & 3, c = tid & 3;
            float2 acc = make_float2(0.f, 0.f);
            #pragma unroll
            for (int k = 0; k < 4; k++)
                acc = cfma2(bufB[(2 * m + 1) * 16 + r * 4 + k],
                            bufB[(2 * m) * 16 + k * 4 + c], acc);
            bufA[tid] = acc;
        }
        BAR128();

        // ---- round 3: 2 products (32 elems) ----
        if (tid < 32) {
            const int m = tid >> 4, r = (tid >> 2) & 3, c = tid & 3;
            float2 acc = make_float2(0.f, 0.f);
            #pragma unroll
            for (int k = 0; k < 4; k++)
                acc = cfma2(bufA[(2 * m + 1) * 16 + r * 4 + k],
                            bufA[(2 * m) * 16 + k * 4 + c], acc);
            bufB[tid] = acc;
        }
        BAR128();

        // ---- round 4: U (16 elems) + T extraction ----
        if (tid < 16) {
            const int r = tid >> 2, c = tid & 3;
            float2 acc = make_float2(0.f, 0.f);
            #pragma unroll
            for (int k = 0; k < 4; k++)
                acc = cfma2(bufB[16 + r * 4 + k], bufB[k * 4 + c], acc);
            bufA[tid] = acc;
            if ((c & 1) == 0)
                sT[(r >> 1) * 4 + (r & 1) * 2 + (c >> 1)] = acc;
        }
        BAR128();

        // ---- quad table Q[q] = T[d3].T[d2].T[d1].T[d0] (64 threads) ----
        if (tid < 64) {
            const int q = tid >> 2;
            const int r = (tid >> 1) & 1, c = tid & 1;
            const int d3 = (q >> 3) & 1, d2 = (q >> 2) & 1;
            const int d1 = (q >> 1) & 1, d0 = q & 1;
            float2 yl0 = cfma2(sT[d3 * 4 + r * 2 + 1], sT[d2 * 4 + 2 + 0],
                               cmul(sT[d3 * 4 + r * 2 + 0], sT[d2 * 4 + 0]));
            float2 yl1 = cfma2(sT[d3 * 4 + r * 2 + 1], sT[d2 * 4 + 2 + 1],
                               cmul(sT[d3 * 4 + r * 2 + 0], sT[d2 * 4 + 1]));
            float2 yr0 = cfma2(sT[d1 * 4 + 0 * 2 + 1], sT[d0 * 4 + 2 + c],
                               cmul(sT[d1 * 4 + 0 * 2 + 0], sT[d0 * 4 + c]));
            float2 yr1 = cfma2(sT[d1 * 4 + 1 * 2 + 1], sT[d0 * 4 + 2 + c],
                               cmul(sT[d1 * 4 + 1 * 2 + 0], sT[d0 * 4 + c]));
            sQ[q * 4 + r * 2 + c] = cfma2(yl1, yr1, cmul(yl0, yr0));
        }
        BAR128();

        // ---- heads, split: lanes 0-3 right half, lanes 4-7 left half ----
        if (tid < 8) {
            if (tid >= 4) {
                // left L = T[x10] . Q[x9x8x7x6]
                const int g = blockIdx.x * 4 + (tid - 4);
                const int q = rev4((g >> 1) & 15) * 4;
                const int b = (g & 1) * 4;
                const int o = (tid - 4) * 4;
                sL[o + 0] = cfma2(sT[b + 1], sQ[q + 2], cmul(sT[b + 0], sQ[q + 0]));
                sL[o + 1] = cfma2(sT[b + 1], sQ[q + 3], cmul(sT[b + 0], sQ[q + 1]));
                sL[o + 2] = cfma2(sT[b + 3], sQ[q + 2], cmul(sT[b + 2], sQ[q + 0]));
                sL[o + 3] = cfma2(sT[b + 3], sQ[q + 3], cmul(sT[b + 2], sQ[q + 1]));
            }
            float2 w0, w1;
            if (tid < 4) {
                // right w = Q[x5x4x3x2] . (T[x1] . v(x0))
                const int g = blockIdx.x * 4 + tid;
                const int x0 = (g >> 10) & 1;
                w0 = bufA[(2 * x0 + 0) * 4 + 0];   // v(x0)_s = U[2x0+s, 0]
                w1 = bufA[(2 * x0 + 1) * 4 + 0];
                {
                    const int b = ((g >> 9) & 1) * 4;
                    float2 n0 = cfma2(sT[b + 1], w1, cmul(sT[b + 0], w0));
                    float2 n1 = cfma2(sT[b + 3], w1, cmul(sT[b + 2], w0));
                    w0 = n0; w1 = n1;
                }
                {
                    const int q = rev4((g >> 5) & 15) * 4;
                    float2 n0 = cfma2(sQ[q + 1], w1, cmul(sQ[q + 0], w0));
                    float2 n1 = cfma2(sQ[q + 3], w1, cmul(sQ[q + 2], w0));
                    w0 = n0; w1 = n1;
                }
            }
            __syncwarp(0xffu);
            if (tid < 4) {
                const int o = tid * 4;
                sAB[tid * 2 + 0] = cfma2(sL[o + 1], w1, cmul(sL[o + 0], w0));
                sAB[tid * 2 + 1] = cfma2(sL[o + 3], w1, cmul(sL[o + 2], w0));
            }
        }
    }
    __syncthreads();   // warps 4-7 wait only here

    // ---- per-thread tail matrix O = Q[qL] . Q[qR]  (j = 2*tid, 2*tid+1) ----
    const int qL = rev4(tid & 15) * 4;
    const int qR = rev4((tid >> 4) & 15) * 4;
    const float2 l00 = sQ[qL + 0], l01 = sQ[qL + 1], l10 = sQ[qL + 2], l11 = sQ[qL + 3];
    const float2 r00 = sQ[qR + 0], r01 = sQ[qR + 1], r10 = sQ[qR + 2], r11 = sQ[qR + 3];
    const float2 o00 = cfma2(l01, r10, cmul(l00, r00));
    const float2 o01 = cfma2(l01, r11, cmul(l00, r01));
    const float2 o10 = cfma2(l11, r10, cmul(l10, r00));
    const float2 o11 = cfma2(l11, r11, cmul(l10, r01));

    // ---- epilogue: 4 groups x 2 outputs, coalesced float2 stores ----
    const long base = (long)blockIdx.x * 2048 + 2 * tid;
    #pragma unroll
    for (int gl = 0; gl < 4; gl++) {
        const float2 a = sAB[gl * 2 + 0];
        const float2 b = sAB[gl * 2 + 1];
        float2 pA = cfma2(o01, b, cmul(o00, a));   // row 0 -> x19 = 0
        float2 pB = cfma2(o11, b, cmul(o10, a));   // row 1 -> x19 = 1
        float2 res;
        res.x = fmaf(pA.x, pA.x, pA.y * pA.y);
        res.y = fmaf(pB.x, pB.x, pB.y * pB.y);
        *(float2*)(out + base + gl * 512) = res;
    }
}

extern "C" void kernel_launch(void* const* d_in, const int* in_sizes, int n_in,
                              void* d_out, int out_size) {
    const float* params = (const float*)d_in[0];
    float* out = (float*)d_out;
    mps_kernel<<<512, 256>>>(params, out);
}

// round 8
// speedup vs baseline: 1.2026x; 1.2026x over previous
#include <cuda_runtime.h>
#include <cstdint>

// ---------------------------------------------------------------------------
// MPS_33930241638883: 20-qubit staircase, K=1. Bond-dim-2 MPS closed form:
//   psi(x0..x19) = e_{x19}^T . T[x18] ... T[x1] . v(x0)
// T[x]_{t,s} = U[2x+t, 2s], v(x0)_s = U[2x0+s, 0]; x_w = bit (19-w) of n.
// n = g*512 + j: g holds x0..x10, j holds x11..x19 (x19 = j bit 0).
//
// Gate build (R7 bugfix): the reference applies the SAME pre before and
// after CNOT.RZ.CNOT (not pre / pre^dagger), so the gate is NOT
// exp(-i t/2 sigma x sigma). Literal algebra of (V0xV1)(ch I - i sh ZxZ)(V0xV1):
//   Vp Z Vp = Z for all paulis; Vp^2 = A_p with A_Z=I, A_X=[[0,1],[-1,0]],
//   A_Y=[[0,-i],[-i,0]]  =>  G = ch*(A_p0 x A_p1) - i*sh*(Z x Z).
// I-containing gates: plain rotation kron (reference applies them directly).
//
// Structure (best measured, round 5): 512 blocks / 256 threads, one wave:
//  - 16 gate matrices in parallel (1 elem/thread), 4-round tree matmul -> U
//    (T[b] extracted in round 4)
//  - quad table Q[d3d2d1d0] = T[d3]T[d2]T[d1]T[d0] (64 threads)
//  - per-thread tail matrix O = Q.Q ; heads ab(g) via 4 chained matvecs
//  - 8 outputs |row(O).ab(g)|^2 per thread, coalesced float2 stores
// ---------------------------------------------------------------------------

__device__ __forceinline__ float2 cmul(float2 a, float2 b) {
    return make_float2(a.x * b.x - a.y * b.y, a.x * b.y + a.y * b.x);
}
__device__ __forceinline__ float2 cfma2(float2 a, float2 b, float2 acc) {
    acc.x = fmaf(a.x, b.x, fmaf(-a.y, b.y, acc.x));
    acc.y = fmaf(a.x, b.y, fmaf(a.y, b.x, acc.y));
    return acc;
}
__device__ __forceinline__ int rev4(int v) {
    return ((v & 1) << 3) | ((v & 2) << 1) | ((v & 4) >> 1) | ((v & 8) >> 3);
}

// rotation 2x2: p=1 RX, p=2 RY, p=3 RZ (verified rounds 1-5)
__device__ __forceinline__ float2 rotR(int p, int i, int j, float ch, float sh) {
    if (p == 1) {
        return (i == j) ? make_float2(ch, 0.f) : make_float2(0.f, -sh);
    } else if (p == 2) {
        if (i == j) return make_float2(ch, 0.f);
        return (i == 0) ? make_float2(-sh, 0.f) : make_float2(sh, 0.f);
    } else {
        if (i != j) return make_float2(0.f, 0.f);
        return (j == 0) ? make_float2(ch, -sh) : make_float2(ch, sh);
    }
}

// A_p = Vp^2: p=1 X -> [[0,1],[-1,0]], p=2 Y -> [[0,-i],[-i,0]], p=3 Z -> I
__device__ __forceinline__ float2 sqA(int p, int i, int j) {
    if (p == 1) {
        if (i == j) return make_float2(0.f, 0.f);
        return make_float2((i == 0) ? 1.f : -1.f, 0.f);
    } else if (p == 2) {
        return (i == j) ? make_float2(0.f, 0.f) : make_float2(0.f, -1.f);
    } else {
        return (i == j) ? make_float2(1.f, 0.f) : make_float2(0.f, 0.f);
    }
}

// element (r,c) of gate gi's 4x4 matrix
__device__ __forceinline__ float2 gateElem(int gi, int r, int c, float ch, float sh) {
    int p0, p1;
    if (gi < 3) { p0 = 0; p1 = gi + 1; }
    else        { p0 = ((gi - 3) >> 2) + 1; p1 = (gi - 3) & 3; }
    const int ar = r >> 1, br = r & 1, ac = c >> 1, bc = c & 1;

    if (p0 == 0)
        return (ar == ac) ? rotR(p1, br, bc, ch, sh) : make_float2(0.f, 0.f);
    if (p1 == 0)
        return (br == bc) ? rotR(p0, ar, ac, ch, sh) : make_float2(0.f, 0.f);

    // G = ch*(A_p0 x A_p1) - i*sh*(Z x Z); (ZxZ)[r,r] = +1 for r in {0,3}
    float2 a = cmul(sqA(p0, ar, ac), sqA(p1, br, bc));
    float2 g = make_float2(ch * a.x, ch * a.y);
    if (r == c)
        g.y -= (r == 0 || r == 3) ? sh : -sh;
    return g;
}

__global__ void __launch_bounds__(256, 8) mps_kernel(const float* __restrict__ params,
                                                     float* __restrict__ out) {
    __shared__ float2 bufA[256];   // 16 gate matrices -> U (ends in bufA[0..15])
    __shared__ float2 bufB[256];
    __shared__ float2 sT[8];       // T[b] at b*4 + row*2 + col
    __shared__ float2 sQ[64];      // Q[q] at q*4 + r*2 + c ; q = d3d2d1d0 (d3 left)
    __shared__ float2 sAB[8];      // head vectors (4 groups x 2)

    const int tid = threadIdx.x;

    // ---- build 15 gate matrices in parallel (16th = identity) ----
    {
        const int m = tid >> 4;          // 0..15
        const int e = tid & 15;
        const int r = e >> 2, c = e & 3;
        float2 g;
        if (m < 15) {
            float th = __ldg(&params[m]);
            float sh, ch;
            sincosf(0.5f * th, &sh, &ch);
            g = gateElem(m, r, c, ch, sh);
        } else {
            g = make_float2((r == c) ? 1.f : 0.f, 0.f);
        }
        bufA[tid] = g;
    }
    __syncthreads();

    // ---- tree-reduce: U = G15 * ... * G0 (4 rounds; T extracted in r4) ----
    {
        float2* src = bufA;
        float2* dst = bufB;
        for (int cnt = 8; cnt >= 1; cnt >>= 1) {
            const int m = tid >> 4;
            if (m < cnt) {
                const int r = (tid >> 2) & 3, c = tid & 3;
                float2 acc = make_float2(0.f, 0.f);
                #pragma unroll
                for (int k = 0; k < 4; k++)
                    acc = cfma2(src[(2 * m + 1) * 16 + r * 4 + k],
                                src[(2 * m) * 16 + k * 4 + c], acc);
                dst[m * 16 + (tid & 15)] = acc;
                if (cnt == 1 && (c & 1) == 0) {
                    // T[b]_{t,s} = U[2b+t, 2s]: b=r>>1, t=r&1, s=c>>1
                    sT[(r >> 1) * 4 + (r & 1) * 2 + (c >> 1)] = acc;
                }
            }
            __syncthreads();
            float2* t = src; src = dst; dst = t;
        }
        // U in bufA[row*4+col], sT populated
    }

    // ---- quad table Q[q] = T[d3].T[d2].T[d1].T[d0], threads 0..63 ----
    if (tid < 64) {
        const int q = tid >> 2;
        const int r = (tid >> 1) & 1, c = tid & 1;
        const int d3 = (q >> 3) & 1, d2 = (q >> 2) & 1;
        const int d1 = (q >> 1) & 1, d0 = q & 1;
        float2 yl0 = cfma2(sT[d3 * 4 + r * 2 + 1], sT[d2 * 4 + 2 + 0],
                           cmul(sT[d3 * 4 + r * 2 + 0], sT[d2 * 4 + 0]));
        float2 yl1 = cfma2(sT[d3 * 4 + r * 2 + 1], sT[d2 * 4 + 2 + 1],
                           cmul(sT[d3 * 4 + r * 2 + 0], sT[d2 * 4 + 1]));
        float2 yr0 = cfma2(sT[d1 * 4 + 0 * 2 + 1], sT[d0 * 4 + 2 + c],
                           cmul(sT[d1 * 4 + 0 * 2 + 0], sT[d0 * 4 + c]));
        float2 yr1 = cfma2(sT[d1 * 4 + 1 * 2 + 1], sT[d0 * 4 + 2 + c],
                           cmul(sT[d1 * 4 + 1 * 2 + 0], sT[d0 * 4 + c]));
        sQ[q * 4 + r * 2 + c] = cfma2(yl1, yr1, cmul(yl0, yr0));
    }
    __syncthreads();

    // ---- per-thread tail matrix O = Q[qL] . Q[qR]  (j = 2*tid, 2*tid+1) ----
    // t bit i = x_{18-i}: qL = x18x17x16x15 = rev4(t&15), qR = x14..x11 = rev4(t>>4)
    const int qL = rev4(tid & 15) * 4;
    const int qR = rev4((tid >> 4) & 15) * 4;
    const float2 l00 = sQ[qL + 0], l01 = sQ[qL + 1], l10 = sQ[qL + 2], l11 = sQ[qL + 3];
    const float2 r00 = sQ[qR + 0], r01 = sQ[qR + 1], r10 = sQ[qR + 2], r11 = sQ[qR + 3];
    const float2 o00 = cfma2(l01, r10, cmul(l00, r00));
    const float2 o01 = cfma2(l01, r11, cmul(l00, r01));
    const float2 o10 = cfma2(l11, r10, cmul(l10, r00));
    const float2 o11 = cfma2(l11, r11, cmul(l10, r01));

    // ---- heads: ab(g) = T[x10] . Q[x9..x6] . Q[x5..x2] . T[x1] . v(x0) ----
    if (tid < 4) {
        const int g = blockIdx.x * 4 + tid;
        const int x0 = (g >> 10) & 1;
        float2 w0 = bufA[(2 * x0 + 0) * 4 + 0];   // v(x0)_s = U[2x0+s, 0]
        float2 w1 = bufA[(2 * x0 + 1) * 4 + 0];
        {   // T[x1]
            const int b = ((g >> 9) & 1) * 4;
            float2 n0 = cfma2(sT[b + 1], w1, cmul(sT[b + 0], w0));
            float2 n1 = cfma2(sT[b + 3], w1, cmul(sT[b + 2], w0));
            w0 = n0; w1 = n1;
        }
        {   // Q[x5x4x3x2]
            const int q = rev4((g >> 5) & 15) * 4;
            float2 n0 = cfma2(sQ[q + 1], w1, cmul(sQ[q + 0], w0));
            float2 n1 = cfma2(sQ[q + 3], w1, cmul(sQ[q + 2], w0));
            w0 = n0; w1 = n1;
        }
        {   // Q[x9x8x7x6]
            const int q = rev4((g >> 1) & 15) * 4;
            float2 n0 = cfma2(sQ[q + 1], w1, cmul(sQ[q + 0], w0));
            float2 n1 = cfma2(sQ[q + 3], w1, cmul(sQ[q + 2], w0));
            w0 = n0; w1 = n1;
        }
        {   // T[x10]
            const int b = (g & 1) * 4;
            float2 n0 = cfma2(sT[b + 1], w1, cmul(sT[b + 0], w0));
            float2 n1 = cfma2(sT[b + 3], w1, cmul(sT[b + 2], w0));
            w0 = n0; w1 = n1;
        }
        sAB[tid * 2 + 0] = w0;
        sAB[tid * 2 + 1] = w1;
    }
    __syncthreads();

    // ---- epilogue: 4 groups x 2 outputs, coalesced float2 stores ----
    const long base = (long)blockIdx.x * 2048 + 2 * tid;
    #pragma unroll
    for (int gl = 0; gl < 4; gl++) {
        const float2 a = sAB[gl * 2 + 0];
        const float2 b = sAB[gl * 2 + 1];
        float2 pA = cfma2(o01, b, cmul(o00, a));   // row 0 -> x19 = 0
        float2 pB = cfma2(o11, b, cmul(o10, a));   // row 1 -> x19 = 1
        float2 res;
        res.x = fmaf(pA.x, pA.x, pA.y * pA.y);
        res.y = fmaf(pB.x, pB.x, pB.y * pB.y);
        *(float2*)(out + base + gl * 512) = res;
    }
}

extern "C" void kernel_launch(void* const* d_in, const int* in_sizes, int n_in,
                              void* d_out, int out_size) {
    const float* params = (const float*)d_in[0];
    float* out = (float*)d_out;
    mps_kernel<<<512, 256>>>(params, out);
}